// round 2
// baseline (speedup 1.0000x reference)
#include <cuda_runtime.h>
#include <math.h>

// ---------------------------------------------------------------------------
// Problem constants (fixed shapes)
// ---------------------------------------------------------------------------
#define BATCH 64
#define T_IN 128
#define T_OUT 32
#define VOCAB 32000
#define EDIM 512
#define HDIM 1024
#define ADIM 512
#define NLAYERS 4
#define XDIM (2*HDIM + EDIM)   // 2560
#define XLDIM (3*HDIM)         // 3072
#define GDIM (4*HDIM)          // 4096

// ---------------------------------------------------------------------------
// Scratch (no allocations allowed -> __device__ globals)
// ---------------------------------------------------------------------------
__device__ float g_enc_proj[T_IN * BATCH * ADIM];    // includes +b1
__device__ float g_x[BATCH * XDIM];                  // [context | emb]
__device__ float g_xl[BATCH * XLDIM];                // [out | context]
__device__ float g_gates[BATCH * GDIM];
__device__ float g_h[NLAYERS * BATCH * HDIM];
__device__ float g_c[NLAYERS * BATCH * HDIM];
__device__ float g_logits[BATCH * VOCAB];
__device__ int   g_tok[BATCH];

// ---------------------------------------------------------------------------
// Init: copy hidden0/cell0 into mutable state, fill prev_tok with eos
// ---------------------------------------------------------------------------
__global__ void init_kernel(const float* __restrict__ h0,
                            const float* __restrict__ c0,
                            const int* __restrict__ eos) {
    int n = NLAYERS * BATCH * HDIM;
    for (int i = blockIdx.x * blockDim.x + threadIdx.x; i < n;
         i += gridDim.x * blockDim.x) {
        g_h[i] = h0[i];
        g_c[i] = c0[i];
    }
    int gid = blockIdx.x * blockDim.x + threadIdx.x;
    if (gid < BATCH) g_tok[gid] = eos[0];
}

// ---------------------------------------------------------------------------
// Templated fp32 SGEMM. TM=64 fixed, BK=16, double-buffered smem.
// C[M x N] = A[M x K] @ B[K x N] (+ A2[M x K2] @ B2[K2 x N]) (+bias1 +bias2)
// All K dims are multiples of BK; M multiple of 64; N multiple of TN.
// Thread layout: NTX = TN/TNT (fast), NTY = TM/TMT. flags bit0 = relu.
// ---------------------------------------------------------------------------
#define FLAG_RELU 1

template<int TN, int TMT, int TNT, int THREADS>
__global__ __launch_bounds__(THREADS)
void sgemm_t(const float* __restrict__ A, const float* __restrict__ B, int K, int ldA,
             const float* __restrict__ A2, const float* __restrict__ B2, int K2, int ldA2,
             const float* __restrict__ bias1, const float* __restrict__ bias2,
             float* __restrict__ C, int N, int flags) {
    constexpr int TM = 64;
    constexpr int BK = 16;
    constexpr int NTX = TN / TNT;
    constexpr int NTY = TM / TMT;
    static_assert(NTX * NTY == THREADS, "thread layout");
    constexpr int PASS_A = (TM * BK) / (THREADS * 4);
    constexpr int PASS_B = (TN * BK) / (THREADS * 4);
    static_assert(PASS_A >= 1 && PASS_B >= 1, "tile too small");
    constexpr int AROWS = THREADS / (BK / 4);      // A rows covered per pass
    constexpr int BROWS = (THREADS * 4) / TN;      // B rows covered per pass

    __shared__ float As[2][BK][TM];
    __shared__ float Bs[2][BK][TN];

    const int m0 = blockIdx.y * TM;
    const int n0 = blockIdx.x * TN;
    const int tid = threadIdx.x;
    const int tx = tid % NTX;
    const int ty = tid / NTX;

    const int arow = tid / (BK / 4);          // 0..AROWS-1
    const int acol = (tid % (BK / 4)) * 4;    // k offset
    const int brow = tid / (TN / 4);          // 0..BROWS-1
    const int bcol = (tid % (TN / 4)) * 4;    // n offset

    float acc[TMT][TNT];
#pragma unroll
    for (int i = 0; i < TMT; i++)
#pragma unroll
        for (int j = 0; j < TNT; j++) acc[i][j] = 0.0f;

    float a_reg[PASS_A][4];
    float b_reg[PASS_B][4];

    auto ldg_tile = [&](const float* Ap, const float* Bp, int lda, int k0) {
#pragma unroll
        for (int p = 0; p < PASS_A; p++) {
            float4 v = *reinterpret_cast<const float4*>(
                &Ap[(size_t)(m0 + arow + p * AROWS) * lda + k0 + acol]);
            a_reg[p][0] = v.x; a_reg[p][1] = v.y; a_reg[p][2] = v.z; a_reg[p][3] = v.w;
        }
#pragma unroll
        for (int p = 0; p < PASS_B; p++) {
            float4 v = *reinterpret_cast<const float4*>(
                &Bp[(size_t)(k0 + brow + p * BROWS) * N + n0 + bcol]);
            b_reg[p][0] = v.x; b_reg[p][1] = v.y; b_reg[p][2] = v.z; b_reg[p][3] = v.w;
        }
    };
    auto sts_tile = [&](int buf) {
#pragma unroll
        for (int p = 0; p < PASS_A; p++)
#pragma unroll
            for (int q = 0; q < 4; q++)
                As[buf][acol + q][arow + p * AROWS] = a_reg[p][q];
#pragma unroll
        for (int p = 0; p < PASS_B; p++)
            *reinterpret_cast<float4*>(&Bs[buf][brow + p * BROWS][bcol]) =
                make_float4(b_reg[p][0], b_reg[p][1], b_reg[p][2], b_reg[p][3]);
    };
    auto compute = [&](int buf) {
#pragma unroll
        for (int k = 0; k < BK; k++) {
            float ar[TMT], br[TNT];
#pragma unroll
            for (int i = 0; i < TMT; i += 4) {
                float4 v = *reinterpret_cast<const float4*>(&As[buf][k][ty * TMT + i]);
                ar[i] = v.x; ar[i + 1] = v.y; ar[i + 2] = v.z; ar[i + 3] = v.w;
            }
#pragma unroll
            for (int j = 0; j < TNT; j += 4) {
                float4 v = *reinterpret_cast<const float4*>(&Bs[buf][k][tx * TNT + j]);
                br[j] = v.x; br[j + 1] = v.y; br[j + 2] = v.z; br[j + 3] = v.w;
            }
#pragma unroll
            for (int i = 0; i < TMT; i++)
#pragma unroll
                for (int j = 0; j < TNT; j++) acc[i][j] += ar[i] * br[j];
        }
    };

    auto run = [&](const float* Ap, const float* Bp, int Kp, int lda) {
        if (Kp <= 0) return;
        const int nk = Kp / BK;
        ldg_tile(Ap, Bp, lda, 0);
        sts_tile(0);
        __syncthreads();
        for (int kt = 0; kt < nk; kt++) {
            const int cur = kt & 1;
            if (kt + 1 < nk) ldg_tile(Ap, Bp, lda, (kt + 1) * BK);
            compute(cur);
            if (kt + 1 < nk) sts_tile(cur ^ 1);
            __syncthreads();
        }
    };

    run(A, B, K, ldA);
    run(A2, B2, K2, ldA2);

#pragma unroll
    for (int i = 0; i < TMT; i++) {
        const int m = m0 + ty * TMT + i;
#pragma unroll
        for (int j = 0; j < TNT; j++) {
            const int n = n0 + tx * TNT + j;
            float v = acc[i][j];
            if (bias1) v += bias1[n];
            if (bias2) v += bias2[n];
            if (flags & FLAG_RELU) v = fmaxf(v, 0.0f);
            C[(size_t)m * N + n] = v;
        }
    }
}

// ---------------------------------------------------------------------------
// Attention kernel: one block per batch element. Also computes q in-block.
//   q[a]      = sum_h out_prev[b,h] * A1[h,a]        (A1[:H])
//   scores[t] = sum_a tanh(q[a] + enc_proj[t,b,a]) * A2[a] + b2 + mask
//   alpha = softmax_t(scores); context[d] = sum_t alpha[t] * enc[t,b,d]
//   x = [context | embedding[tok]];  xl[1024:3072] = context
// ---------------------------------------------------------------------------
__global__ __launch_bounds__(256)
void att_kernel(const float* __restrict__ enc, const float* __restrict__ ison,
                const float* __restrict__ emb, const float* __restrict__ A1,
                const float* __restrict__ A2v, const float* __restrict__ b2,
                const float* __restrict__ outprev) {
    const int b = blockIdx.x;
    const int tid = threadIdx.x;
    const int lane = tid & 31;
    const int w = tid >> 5;

    __shared__ float s_out[HDIM];
    __shared__ float s_q[ADIM];
    __shared__ float s_a2[ADIM];
    __shared__ float s_sc[T_IN];

    for (int i = tid; i < HDIM; i += 256) s_out[i] = outprev[(size_t)b * HDIM + i];
    for (int i = tid; i < ADIM; i += 256) s_a2[i] = A2v[i];
    __syncthreads();

    // q = out_prev(1x1024) @ A1[:H](1024x512); each thread owns cols tid, tid+256
    {
        float q0 = 0.0f, q1 = 0.0f;
        const float* a1p = A1;
#pragma unroll 8
        for (int h = 0; h < HDIM; h++) {
            float ov = s_out[h];
            q0 += ov * a1p[tid];
            q1 += ov * a1p[tid + 256];
            a1p += ADIM;
        }
        s_q[tid] = q0;
        s_q[tid + 256] = q1;
    }
    __syncthreads();

    const float b2v = b2[0];
    // scores: per-warp over t
    for (int t = w; t < T_IN; t += 8) {
        const float* ep = g_enc_proj + (size_t)(t * BATCH + b) * ADIM;
        float v = 0.0f;
#pragma unroll
        for (int i = 0; i < ADIM / 32; i++) {
            int a = lane + 32 * i;
            v += tanhf(s_q[a] + ep[a]) * s_a2[a];
        }
#pragma unroll
        for (int o = 16; o > 0; o >>= 1) v += __shfl_xor_sync(0xffffffffu, v, o);
        if (lane == 0) {
            float mb = (1.0f - ison[t * BATCH + b]) * (-1e30f);
            s_sc[t] = v + b2v + mb;
        }
    }
    __syncthreads();

    // softmax over T_IN=128 in warp 0
    if (w == 0) {
        float x0 = s_sc[lane], x1 = s_sc[lane + 32], x2 = s_sc[lane + 64], x3 = s_sc[lane + 96];
        float m = fmaxf(fmaxf(x0, x1), fmaxf(x2, x3));
#pragma unroll
        for (int o = 16; o > 0; o >>= 1) m = fmaxf(m, __shfl_xor_sync(0xffffffffu, m, o));
        float e0 = expf(x0 - m), e1 = expf(x1 - m), e2 = expf(x2 - m), e3 = expf(x3 - m);
        float s = e0 + e1 + e2 + e3;
#pragma unroll
        for (int o = 16; o > 0; o >>= 1) s += __shfl_xor_sync(0xffffffffu, s, o);
        float inv = 1.0f / s;
        s_sc[lane] = e0 * inv;
        s_sc[lane + 32] = e1 * inv;
        s_sc[lane + 64] = e2 * inv;
        s_sc[lane + 96] = e3 * inv;
    }
    __syncthreads();

    // context: 2048 dims, 8 per thread
    float acc[8];
#pragma unroll
    for (int i = 0; i < 8; i++) acc[i] = 0.0f;
    for (int t = 0; t < T_IN; t++) {
        float al = s_sc[t];
        const float* er = enc + (size_t)(t * BATCH + b) * (2 * HDIM);
#pragma unroll
        for (int i = 0; i < 8; i++) acc[i] += al * er[tid + 256 * i];
    }
#pragma unroll
    for (int i = 0; i < 8; i++) {
        int d = tid + 256 * i;
        g_x[(size_t)b * XDIM + d] = acc[i];
        g_xl[(size_t)b * XLDIM + HDIM + d] = acc[i];
    }

    // embedding gather
    int token = g_tok[b];
    const float* erow = emb + (size_t)token * EDIM;
    for (int e = tid; e < EDIM; e += 256)
        g_x[(size_t)b * XDIM + 2 * HDIM + e] = erow[e];
}

// ---------------------------------------------------------------------------
// LSTM pointwise: gates (i,f,g,o) -> new c, h. Optionally mirror h into xl.
// ---------------------------------------------------------------------------
__device__ __forceinline__ float sigf(float x) { return 1.0f / (1.0f + expf(-x)); }

__global__ __launch_bounds__(256)
void lstm_pw_kernel(float* __restrict__ h, float* __restrict__ c, int writeXl) {
    int idx = blockIdx.x * 256 + threadIdx.x;   // 0..65535
    int b = idx >> 10;
    int j = idx & 1023;
    const float* g = g_gates + (size_t)b * GDIM;
    float ig = sigf(g[j]);
    float fg = sigf(g[HDIM + j]);
    float gg = tanhf(g[2 * HDIM + j]);
    float og = sigf(g[3 * HDIM + j]);
    float cn = fg * c[idx] + ig * gg;
    float hn = og * tanhf(cn);
    c[idx] = cn;
    h[idx] = hn;
    if (writeXl) g_xl[(size_t)b * XLDIM + j] = hn;   // xl[:, 0:1024] = out
}

// ---------------------------------------------------------------------------
// Softmax over V + argmax(prob) with first-index tie-break (jnp.argmax)
// ---------------------------------------------------------------------------
__global__ __launch_bounds__(256)
void softmax_argmax_kernel(float* __restrict__ out, int step) {
    const int b = blockIdx.x;
    const int tid = threadIdx.x;
    const int lane = tid & 31;
    const int w = tid >> 5;
    const float* row = g_logits + (size_t)b * VOCAB;
    float* orow = out + ((size_t)step * BATCH + b) * VOCAB;

    __shared__ float sred[8];
    __shared__ float s_stat[2];

    // pass 1: max
    float m = -INFINITY;
    for (int j = tid; j < VOCAB; j += 256) m = fmaxf(m, row[j]);
#pragma unroll
    for (int o = 16; o > 0; o >>= 1) m = fmaxf(m, __shfl_xor_sync(0xffffffffu, m, o));
    if (lane == 0) sred[w] = m;
    __syncthreads();
    if (tid == 0) {
        float mm = sred[0];
#pragma unroll
        for (int i = 1; i < 8; i++) mm = fmaxf(mm, sred[i]);
        s_stat[0] = mm;
    }
    __syncthreads();
    m = s_stat[0];

    // pass 2: sum of exp
    float s = 0.0f;
    for (int j = tid; j < VOCAB; j += 256) s += expf(row[j] - m);
#pragma unroll
    for (int o = 16; o > 0; o >>= 1) s += __shfl_xor_sync(0xffffffffu, s, o);
    __syncthreads();
    if (lane == 0) sred[w] = s;
    __syncthreads();
    if (tid == 0) {
        float ss = 0.0f;
#pragma unroll
        for (int i = 0; i < 8; i++) ss += sred[i];
        s_stat[1] = ss;
    }
    __syncthreads();
    float inv = 1.0f / s_stat[1];

    // pass 3: write probs + argmax(prob), first index wins ties
    float bestv = -1.0f;
    int besti = 0x7fffffff;
    for (int j = tid; j < VOCAB; j += 256) {
        float p = expf(row[j] - m) * inv;
        orow[j] = p;
        if (p > bestv) { bestv = p; besti = j; }
    }
    __shared__ float sv[256];
    __shared__ int si[256];
    sv[tid] = bestv;
    si[tid] = besti;
    __syncthreads();
    for (int st = 128; st > 0; st >>= 1) {
        if (tid < st) {
            float v2 = sv[tid + st];
            int i2 = si[tid + st];
            if (v2 > sv[tid] || (v2 == sv[tid] && i2 < si[tid])) {
                sv[tid] = v2;
                si[tid] = i2;
            }
        }
        __syncthreads();
    }
    if (tid == 0) g_tok[b] = si[0];
}

// ---------------------------------------------------------------------------
// Launch sequence (fully unrolled 32 steps; graph-capturable, alloc-free)
// ---------------------------------------------------------------------------
extern "C" void kernel_launch(void* const* d_in, const int* in_sizes, int n_in,
                              void* d_out, int out_size) {
    const float* enc     = (const float*)d_in[0];   // (128,64,2048)
    const float* ison    = (const float*)d_in[1];   // (128,64)
    const float* emb     = (const float*)d_in[2];   // (32000,512)
    const float* A1      = (const float*)d_in[3];   // (3072,512)
    const float* b1      = (const float*)d_in[4];   // (512)
    const float* A2v     = (const float*)d_in[5];   // (512,1)
    const float* b2      = (const float*)d_in[6];   // (1)
    const float* Wih0    = (const float*)d_in[7];   // (2560,4096)
    const float* WihR    = (const float*)d_in[8];   // (3,1024,4096)
    const float* Whh     = (const float*)d_in[9];   // (4,1024,4096)
    const float* bih     = (const float*)d_in[10];  // (4,4096)
    const float* bhh     = (const float*)d_in[11];  // (4,4096)
    const float* Wl      = (const float*)d_in[12];  // (3072,32000)
    const float* bl      = (const float*)d_in[13];  // (32000)
    const float* h0      = (const float*)d_in[14];  // (4,64,1024)
    const float* c0      = (const float*)d_in[15];  // (4,64,1024)
    const float* outr0   = (const float*)d_in[16];  // (64,1024)
    const int*   eos     = (const int*)d_in[17];    // scalar
    float* out = (float*)d_out;

    float* eproj;  cudaGetSymbolAddress((void**)&eproj,  g_enc_proj);
    float* xbuf;   cudaGetSymbolAddress((void**)&xbuf,   g_x);
    float* xlbuf;  cudaGetSymbolAddress((void**)&xlbuf,  g_xl);
    float* gates;  cudaGetSymbolAddress((void**)&gates,  g_gates);
    float* hbuf;   cudaGetSymbolAddress((void**)&hbuf,   g_h);
    float* cbuf;   cudaGetSymbolAddress((void**)&cbuf,   g_c);
    float* logits; cudaGetSymbolAddress((void**)&logits, g_logits);

    init_kernel<<<256, 256>>>(h0, c0, eos);

    // enc_proj = encoder(8192x2048) @ A1[H:](2048x512) + b1   [wide tiles]
    sgemm_t<128, 4, 8, 256><<<dim3(ADIM / 128, (T_IN * BATCH) / 64), 256>>>(
        enc, A1 + (size_t)HDIM * ADIM, 2 * HDIM, 2 * HDIM,
        nullptr, nullptr, 0, 0,
        b1, nullptr, eproj, ADIM, 0);

    for (int step = 0; step < T_OUT; step++) {
        const float* outprev = (step == 0) ? outr0 : (hbuf + 3 * BATCH * HDIM);

        att_kernel<<<BATCH, 256>>>(enc, ison, emb, A1, A2v, b2, outprev);

        for (int l = 0; l < NLAYERS; l++) {
            const float* Ain = (l == 0) ? xbuf : (hbuf + (size_t)(l - 1) * BATCH * HDIM);
            int K1 = (l == 0) ? XDIM : HDIM;
            const float* Bih = (l == 0) ? Wih0 : (WihR + (size_t)(l - 1) * HDIM * GDIM);
            // gates(64x4096) = x @ W_ih + h @ W_hh + b_ih + b_hh  [narrow tiles, 128 blocks]
            sgemm_t<32, 4, 4, 128><<<dim3(GDIM / 32, 1), 128>>>(
                Ain, Bih, K1, K1,
                hbuf + (size_t)l * BATCH * HDIM, Whh + (size_t)l * HDIM * GDIM, HDIM, HDIM,
                bih + (size_t)l * GDIM, bhh + (size_t)l * GDIM,
                gates, GDIM, 0);
            lstm_pw_kernel<<<(BATCH * HDIM) / 256, 256>>>(
                hbuf + (size_t)l * BATCH * HDIM, cbuf + (size_t)l * BATCH * HDIM,
                (l == NLAYERS - 1) ? 1 : 0);
        }

        // logits = relu(xl(64x3072) @ Wl(3072x32000) + bl)   [wide tiles, 250 blocks]
        sgemm_t<128, 4, 8, 256><<<dim3(VOCAB / 128, 1), 256>>>(
            xlbuf, Wl, XLDIM, XLDIM,
            nullptr, nullptr, 0, 0,
            bl, nullptr, logits, VOCAB, FLAG_RELU);

        softmax_argmax_kernel<<<BATCH, 256>>>(out, step);
    }
    (void)in_sizes; (void)n_in; (void)out_size;
}

// round 9
// speedup vs baseline: 1.2929x; 1.2929x over previous
#include <cuda_runtime.h>
#include <math.h>

// ---------------------------------------------------------------------------
// Problem constants (fixed shapes)
// ---------------------------------------------------------------------------
#define BATCH 64
#define T_IN 128
#define T_OUT 32
#define VOCAB 32000
#define EDIM 512
#define HDIM 1024
#define ADIM 512
#define NLAYERS 4
#define XDIM (2*HDIM + EDIM)   // 2560
#define XLDIM (3*HDIM)         // 3072
#define GDIM (4*HDIM)          // 4096
#define KSPLIT 8

// ---------------------------------------------------------------------------
// Packed fp32x2 helpers (sm_100+: dual-lane fp32 FMA, bit-identical to scalar)
// ---------------------------------------------------------------------------
__device__ __forceinline__ unsigned long long pack2(float lo, float hi) {
    unsigned long long r;
    asm("mov.b64 %0, {%1, %2};" : "=l"(r) : "f"(lo), "f"(hi));
    return r;
}
__device__ __forceinline__ void unpack2(unsigned long long v, float& lo, float& hi) {
    asm("mov.b64 {%0, %1}, %2;" : "=f"(lo), "=f"(hi) : "l"(v));
}
__device__ __forceinline__ unsigned long long ffma2(unsigned long long a,
                                                    unsigned long long b,
                                                    unsigned long long c) {
    unsigned long long d;
    asm("fma.rn.f32x2 %0, %1, %2, %3;" : "=l"(d) : "l"(a), "l"(b), "l"(c));
    return d;
}

// ---------------------------------------------------------------------------
// Scratch (no allocations allowed -> __device__ globals)
// ---------------------------------------------------------------------------
__device__ float g_enc_proj[T_IN * BATCH * ADIM];    // includes +b1
__device__ float g_x[BATCH * XDIM];                  // [context | emb]
__device__ float g_xl[BATCH * XLDIM];                // [out | context]
__device__ float g_gpart[KSPLIT * BATCH * GDIM];     // split-K partials (8MB)
__device__ float g_h[NLAYERS * BATCH * HDIM];
__device__ float g_c[NLAYERS * BATCH * HDIM];
__device__ float g_logits[BATCH * VOCAB];
__device__ int   g_tok[BATCH];

// ---------------------------------------------------------------------------
// Init: copy hidden0/cell0 into mutable state, fill prev_tok with eos
// ---------------------------------------------------------------------------
__global__ void init_kernel(const float* __restrict__ h0,
                            const float* __restrict__ c0,
                            const int* __restrict__ eos) {
    int n = NLAYERS * BATCH * HDIM;
    for (int i = blockIdx.x * blockDim.x + threadIdx.x; i < n;
         i += gridDim.x * blockDim.x) {
        g_h[i] = h0[i];
        g_c[i] = c0[i];
    }
    int gid = blockIdx.x * blockDim.x + threadIdx.x;
    if (gid < BATCH) g_tok[gid] = eos[0];
}

// ---------------------------------------------------------------------------
// Templated fp32 SGEMM. TM=64 fixed, BK=16, double-buffered smem, FFMA2 core.
// (used for enc_proj and logits). TNT must be a multiple of 4.
// ---------------------------------------------------------------------------
#define FLAG_RELU 1

template<int TN, int TMT, int TNT, int THREADS>
__global__ __launch_bounds__(THREADS)
void sgemm_t(const float* __restrict__ A, const float* __restrict__ B, int K, int ldA,
             const float* __restrict__ bias1,
             float* __restrict__ C, int N, int flags) {
    constexpr int TM = 64;
    constexpr int BK = 16;
    constexpr int NTX = TN / TNT;
    constexpr int NTY = TM / TMT;
    static_assert(NTX * NTY == THREADS, "thread layout");
    static_assert((TNT % 4) == 0 && (TMT % 4) == 0, "frag multiple of 4");
    constexpr int PASS_A = (TM * BK) / (THREADS * 4);
    constexpr int PASS_B = (TN * BK) / (THREADS * 4);
    static_assert(PASS_A >= 1 && PASS_B >= 1, "tile too small");
    constexpr int AROWS = THREADS / (BK / 4);
    constexpr int BROWS = (THREADS * 4) / TN;

    __shared__ float As[2][BK][TM];
    __shared__ float Bs[2][BK][TN];

    const int m0 = blockIdx.y * TM;
    const int n0 = blockIdx.x * TN;
    const int tid = threadIdx.x;
    const int tx = tid % NTX;
    const int ty = tid / NTX;

    const int arow = tid / (BK / 4);
    const int acol = (tid % (BK / 4)) * 4;
    const int brow = tid / (TN / 4);
    const int bcol = (tid % (TN / 4)) * 4;

    // packed accumulators: pairs along n
    unsigned long long acc2[TMT][TNT / 2];
#pragma unroll
    for (int i = 0; i < TMT; i++)
#pragma unroll
        for (int j = 0; j < TNT / 2; j++) acc2[i][j] = 0ull;

    float a_reg[PASS_A][4];
    float b_reg[PASS_B][4];

    auto ldg_tile = [&](int k0) {
#pragma unroll
        for (int p = 0; p < PASS_A; p++) {
            float4 v = *reinterpret_cast<const float4*>(
                &A[(size_t)(m0 + arow + p * AROWS) * ldA + k0 + acol]);
            a_reg[p][0] = v.x; a_reg[p][1] = v.y; a_reg[p][2] = v.z; a_reg[p][3] = v.w;
        }
#pragma unroll
        for (int p = 0; p < PASS_B; p++) {
            float4 v = *reinterpret_cast<const float4*>(
                &B[(size_t)(k0 + brow + p * BROWS) * N + n0 + bcol]);
            b_reg[p][0] = v.x; b_reg[p][1] = v.y; b_reg[p][2] = v.z; b_reg[p][3] = v.w;
        }
    };
    auto sts_tile = [&](int buf) {
#pragma unroll
        for (int p = 0; p < PASS_A; p++)
#pragma unroll
            for (int q = 0; q < 4; q++)
                As[buf][acol + q][arow + p * AROWS] = a_reg[p][q];
#pragma unroll
        for (int p = 0; p < PASS_B; p++)
            *reinterpret_cast<float4*>(&Bs[buf][brow + p * BROWS][bcol]) =
                make_float4(b_reg[p][0], b_reg[p][1], b_reg[p][2], b_reg[p][3]);
    };
    auto compute = [&](int buf) {
#pragma unroll
        for (int k = 0; k < BK; k++) {
            float ar[TMT];
#pragma unroll
            for (int i = 0; i < TMT; i += 4) {
                float4 v = *reinterpret_cast<const float4*>(&As[buf][k][ty * TMT + i]);
                ar[i] = v.x; ar[i + 1] = v.y; ar[i + 2] = v.z; ar[i + 3] = v.w;
            }
            unsigned long long b2[TNT / 2];
#pragma unroll
            for (int j = 0; j < TNT; j += 4) {
                float4 v = *reinterpret_cast<const float4*>(&Bs[buf][k][tx * TNT + j]);
                b2[j / 2]     = pack2(v.x, v.y);
                b2[j / 2 + 1] = pack2(v.z, v.w);
            }
#pragma unroll
            for (int i = 0; i < TMT; i++) {
                unsigned long long a2 = pack2(ar[i], ar[i]);
#pragma unroll
                for (int j = 0; j < TNT / 2; j++)
                    acc2[i][j] = ffma2(a2, b2[j], acc2[i][j]);
            }
        }
    };

    const int nk = K / BK;
    ldg_tile(0);
    sts_tile(0);
    __syncthreads();
    for (int kt = 0; kt < nk; kt++) {
        const int cur = kt & 1;
        if (kt + 1 < nk) ldg_tile((kt + 1) * BK);
        compute(cur);
        if (kt + 1 < nk) sts_tile(cur ^ 1);
        __syncthreads();
    }

#pragma unroll
    for (int i = 0; i < TMT; i++) {
        const int m = m0 + ty * TMT + i;
#pragma unroll
        for (int j = 0; j < TNT; j += 2) {
            float v0, v1;
            unpack2(acc2[i][j / 2], v0, v1);
            const int n = n0 + tx * TNT + j;
            if (bias1) { v0 += bias1[n]; v1 += bias1[n + 1]; }
            if (flags & FLAG_RELU) { v0 = fmaxf(v0, 0.0f); v1 = fmaxf(v1, 0.0f); }
            C[(size_t)m * N + n] = v0;
            C[(size_t)m * N + n + 1] = v1;
        }
    }
}

// ---------------------------------------------------------------------------
// Split-K gates GEMM: Cpart[z] = x[:, zslice] @ W_ih[zslice] + h[:, zslice] @ W_hh[zslice]
// TM=64 (all of M), TN=64, BK=16, 256 threads, KSPLIT z-slices, FFMA2 core.
// Grid: (GDIM/64, KSPLIT) = (64, 8) = 512 blocks -> ~3.5 blocks/SM.
// ---------------------------------------------------------------------------
__global__ __launch_bounds__(256)
void gates_splitk_kernel(const float* __restrict__ A, const float* __restrict__ B, int K1,
                         const float* __restrict__ A2, const float* __restrict__ B2) {
    constexpr int TM = 64, TN = 64, BK = 16;
    const int z = blockIdx.y;
    const int n0 = blockIdx.x * TN;
    const int tid = threadIdx.x;
    const int tx = tid & 15;       // 0..15
    const int ty = tid >> 4;       // 0..15

    __shared__ float As[2][BK][TM];
    __shared__ float Bs[2][BK][TN];

    unsigned long long acc2[4][2];
#pragma unroll
    for (int i = 0; i < 4; i++) { acc2[i][0] = 0ull; acc2[i][1] = 0ull; }

    const int arow = tid >> 2;            // 0..63
    const int acol = (tid & 3) * 4;       // k offset
    const int brow = tid >> 4;            // 0..15
    const int bcol = (tid & 15) * 4;      // n offset

    float a_reg[4];
    float b_reg[4];

    const float* Ap;
    const float* Bp;
    int lda;

    auto ldg_tile = [&](int k0) {
        float4 v = __ldg(reinterpret_cast<const float4*>(
            &Ap[(size_t)arow * lda + k0 + acol]));
        a_reg[0] = v.x; a_reg[1] = v.y; a_reg[2] = v.z; a_reg[3] = v.w;
        float4 w = __ldg(reinterpret_cast<const float4*>(
            &Bp[(size_t)(k0 + brow) * GDIM + n0 + bcol]));
        b_reg[0] = w.x; b_reg[1] = w.y; b_reg[2] = w.z; b_reg[3] = w.w;
    };
    auto sts_tile = [&](int buf) {
#pragma unroll
        for (int q = 0; q < 4; q++) As[buf][acol + q][arow] = a_reg[q];
        *reinterpret_cast<float4*>(&Bs[buf][brow][bcol]) =
            make_float4(b_reg[0], b_reg[1], b_reg[2], b_reg[3]);
    };
    auto compute = [&](int buf) {
#pragma unroll
        for (int k = 0; k < BK; k++) {
            float4 av = *reinterpret_cast<const float4*>(&As[buf][k][ty * 4]);
            float4 bv = *reinterpret_cast<const float4*>(&Bs[buf][k][tx * 4]);
            unsigned long long b20 = pack2(bv.x, bv.y);
            unsigned long long b21 = pack2(bv.z, bv.w);
            float ar[4] = {av.x, av.y, av.z, av.w};
#pragma unroll
            for (int i = 0; i < 4; i++) {
                unsigned long long a2 = pack2(ar[i], ar[i]);
                acc2[i][0] = ffma2(a2, b20, acc2[i][0]);
                acc2[i][1] = ffma2(a2, b21, acc2[i][1]);
            }
        }
    };
    auto run = [&](int Kp) {
        const int nk = Kp / BK;
        ldg_tile(0);
        sts_tile(0);
        __syncthreads();
        for (int kt = 0; kt < nk; kt++) {
            const int cur = kt & 1;
            if (kt + 1 < nk) ldg_tile((kt + 1) * BK);
            compute(cur);
            if (kt + 1 < nk) sts_tile(cur ^ 1);
            __syncthreads();
        }
    };

    // slice 1: x @ W_ih
    const int ks1 = K1 / KSPLIT;
    Ap = A + (size_t)z * ks1;
    Bp = B + (size_t)z * ks1 * GDIM;
    lda = K1;
    run(ks1);
    // slice 2: h @ W_hh  (K2 = HDIM)
    const int ks2 = HDIM / KSPLIT;
    Ap = A2 + (size_t)z * ks2;
    Bp = B2 + (size_t)z * ks2 * GDIM;
    lda = HDIM;
    run(ks2);

    float* Cp = g_gpart + (size_t)z * BATCH * GDIM;
#pragma unroll
    for (int i = 0; i < 4; i++) {
        const int m = ty * 4 + i;
        float v0, v1, v2, v3;
        unpack2(acc2[i][0], v0, v1);
        unpack2(acc2[i][1], v2, v3);
        *reinterpret_cast<float4*>(&Cp[(size_t)m * GDIM + n0 + tx * 4]) =
            make_float4(v0, v1, v2, v3);
    }
}

// ---------------------------------------------------------------------------
// Fused split-K reduce + LSTM pointwise. Vectorized: one thread per (b, 4 j's).
// gates order: i, f, g, o at offsets j, H+j, 2H+j, 3H+j.
// ---------------------------------------------------------------------------
__device__ __forceinline__ float sigf(float x) { return 1.0f / (1.0f + expf(-x)); }

__global__ __launch_bounds__(256)
void reduce_lstm_kernel(const float* __restrict__ bih, const float* __restrict__ bhh,
                        float* __restrict__ h, float* __restrict__ c, int writeXl) {
    int v = blockIdx.x * 256 + threadIdx.x;     // 0..16383 (vector index)
    int b = v >> 8;                              // 256 vectors per batch row
    int j = (v & 255) * 4;

    float4 gi = *reinterpret_cast<const float4*>(&bih[j]);
    float4 gf = *reinterpret_cast<const float4*>(&bih[HDIM + j]);
    float4 gg = *reinterpret_cast<const float4*>(&bih[2 * HDIM + j]);
    float4 go = *reinterpret_cast<const float4*>(&bih[3 * HDIM + j]);
    {
        float4 t;
        t = *reinterpret_cast<const float4*>(&bhh[j]);
        gi.x += t.x; gi.y += t.y; gi.z += t.z; gi.w += t.w;
        t = *reinterpret_cast<const float4*>(&bhh[HDIM + j]);
        gf.x += t.x; gf.y += t.y; gf.z += t.z; gf.w += t.w;
        t = *reinterpret_cast<const float4*>(&bhh[2 * HDIM + j]);
        gg.x += t.x; gg.y += t.y; gg.z += t.z; gg.w += t.w;
        t = *reinterpret_cast<const float4*>(&bhh[3 * HDIM + j]);
        go.x += t.x; go.y += t.y; go.z += t.z; go.w += t.w;
    }
#pragma unroll
    for (int z = 0; z < KSPLIT; z++) {
        const float* p = g_gpart + (size_t)(z * BATCH + b) * GDIM;
        float4 t;
        t = *reinterpret_cast<const float4*>(&p[j]);
        gi.x += t.x; gi.y += t.y; gi.z += t.z; gi.w += t.w;
        t = *reinterpret_cast<const float4*>(&p[HDIM + j]);
        gf.x += t.x; gf.y += t.y; gf.z += t.z; gf.w += t.w;
        t = *reinterpret_cast<const float4*>(&p[2 * HDIM + j]);
        gg.x += t.x; gg.y += t.y; gg.z += t.z; gg.w += t.w;
        t = *reinterpret_cast<const float4*>(&p[3 * HDIM + j]);
        go.x += t.x; go.y += t.y; go.z += t.z; go.w += t.w;
    }
    size_t idx = (size_t)b * HDIM + j;
    float4 cv = *reinterpret_cast<const float4*>(&c[idx]);
    float4 cn, hn;
    cn.x = sigf(gf.x) * cv.x + sigf(gi.x) * tanhf(gg.x);
    cn.y = sigf(gf.y) * cv.y + sigf(gi.y) * tanhf(gg.y);
    cn.z = sigf(gf.z) * cv.z + sigf(gi.z) * tanhf(gg.z);
    cn.w = sigf(gf.w) * cv.w + sigf(gi.w) * tanhf(gg.w);
    hn.x = sigf(go.x) * tanhf(cn.x);
    hn.y = sigf(go.y) * tanhf(cn.y);
    hn.z = sigf(go.z) * tanhf(cn.z);
    hn.w = sigf(go.w) * tanhf(cn.w);
    *reinterpret_cast<float4*>(&c[idx]) = cn;
    *reinterpret_cast<float4*>(&h[idx]) = hn;
    if (writeXl)
        *reinterpret_cast<float4*>(&g_xl[(size_t)b * XLDIM + j]) = hn;
}

// ---------------------------------------------------------------------------
// Attention kernel: one block per batch element. Also computes q in-block.
// ---------------------------------------------------------------------------
__global__ __launch_bounds__(256)
void att_kernel(const float* __restrict__ enc, const float* __restrict__ ison,
                const float* __restrict__ emb, const float* __restrict__ A1,
                const float* __restrict__ A2v, const float* __restrict__ b2,
                const float* __restrict__ outprev) {
    const int b = blockIdx.x;
    const int tid = threadIdx.x;
    const int lane = tid & 31;
    const int w = tid >> 5;

    __shared__ float s_out[HDIM];
    __shared__ float s_q[ADIM];
    __shared__ float s_a2[ADIM];
    __shared__ float s_sc[T_IN];

    for (int i = tid; i < HDIM; i += 256) s_out[i] = outprev[(size_t)b * HDIM + i];
    for (int i = tid; i < ADIM; i += 256) s_a2[i] = A2v[i];
    __syncthreads();

    // q = out_prev(1x1024) @ A1[:H](1024x512); each thread owns cols tid, tid+256
    {
        float q0 = 0.0f, q1 = 0.0f;
        const float* a1p = A1;
#pragma unroll 8
        for (int h = 0; h < HDIM; h++) {
            float ov = s_out[h];
            q0 += ov * a1p[tid];
            q1 += ov * a1p[tid + 256];
            a1p += ADIM;
        }
        s_q[tid] = q0;
        s_q[tid + 256] = q1;
    }
    __syncthreads();

    const float b2v = b2[0];
    // scores: per-warp over t
    for (int t = w; t < T_IN; t += 8) {
        const float* ep = g_enc_proj + (size_t)(t * BATCH + b) * ADIM;
        float v = 0.0f;
#pragma unroll
        for (int i = 0; i < ADIM / 32; i++) {
            int a = lane + 32 * i;
            v += tanhf(s_q[a] + ep[a]) * s_a2[a];
        }
#pragma unroll
        for (int o = 16; o > 0; o >>= 1) v += __shfl_xor_sync(0xffffffffu, v, o);
        if (lane == 0) {
            float mb = (1.0f - ison[t * BATCH + b]) * (-1e30f);
            s_sc[t] = v + b2v + mb;
        }
    }
    __syncthreads();

    // softmax over T_IN=128 in warp 0
    if (w == 0) {
        float x0 = s_sc[lane], x1 = s_sc[lane + 32], x2 = s_sc[lane + 64], x3 = s_sc[lane + 96];
        float m = fmaxf(fmaxf(x0, x1), fmaxf(x2, x3));
#pragma unroll
        for (int o = 16; o > 0; o >>= 1) m = fmaxf(m, __shfl_xor_sync(0xffffffffu, m, o));
        float e0 = expf(x0 - m), e1 = expf(x1 - m), e2 = expf(x2 - m), e3 = expf(x3 - m);
        float s = e0 + e1 + e2 + e3;
#pragma unroll
        for (int o = 16; o > 0; o >>= 1) s += __shfl_xor_sync(0xffffffffu, s, o);
        float inv = 1.0f / s;
        s_sc[lane] = e0 * inv;
        s_sc[lane + 32] = e1 * inv;
        s_sc[lane + 64] = e2 * inv;
        s_sc[lane + 96] = e3 * inv;
    }
    __syncthreads();

    // context: 2048 dims, 8 per thread
    float acc[8];
#pragma unroll
    for (int i = 0; i < 8; i++) acc[i] = 0.0f;
    for (int t = 0; t < T_IN; t++) {
        float al = s_sc[t];
        const float* er = enc + (size_t)(t * BATCH + b) * (2 * HDIM);
#pragma unroll
        for (int i = 0; i < 8; i++) acc[i] += al * er[tid + 256 * i];
    }
#pragma unroll
    for (int i = 0; i < 8; i++) {
        int d = tid + 256 * i;
        g_x[(size_t)b * XDIM + d] = acc[i];
        g_xl[(size_t)b * XLDIM + HDIM + d] = acc[i];
    }

    // embedding gather
    int token = g_tok[b];
    const float* erow = emb + (size_t)token * EDIM;
    for (int e = tid; e < EDIM; e += 256)
        g_x[(size_t)b * XDIM + 2 * HDIM + e] = erow[e];
}

// ---------------------------------------------------------------------------
// Softmax over V + argmax(prob) with first-index tie-break (jnp.argmax)
// ---------------------------------------------------------------------------
__global__ __launch_bounds__(256)
void softmax_argmax_kernel(float* __restrict__ out, int step) {
    const int b = blockIdx.x;
    const int tid = threadIdx.x;
    const int lane = tid & 31;
    const int w = tid >> 5;
    const float* row = g_logits + (size_t)b * VOCAB;
    float* orow = out + ((size_t)step * BATCH + b) * VOCAB;

    __shared__ float sred[8];
    __shared__ float s_stat[2];

    float m = -INFINITY;
    for (int j = tid; j < VOCAB; j += 256) m = fmaxf(m, row[j]);
#pragma unroll
    for (int o = 16; o > 0; o >>= 1) m = fmaxf(m, __shfl_xor_sync(0xffffffffu, m, o));
    if (lane == 0) sred[w] = m;
    __syncthreads();
    if (tid == 0) {
        float mm = sred[0];
#pragma unroll
        for (int i = 1; i < 8; i++) mm = fmaxf(mm, sred[i]);
        s_stat[0] = mm;
    }
    __syncthreads();
    m = s_stat[0];

    float s = 0.0f;
    for (int j = tid; j < VOCAB; j += 256) s += expf(row[j] - m);
#pragma unroll
    for (int o = 16; o > 0; o >>= 1) s += __shfl_xor_sync(0xffffffffu, s, o);
    __syncthreads();
    if (lane == 0) sred[w] = s;
    __syncthreads();
    if (tid == 0) {
        float ss = 0.0f;
#pragma unroll
        for (int i = 0; i < 8; i++) ss += sred[i];
        s_stat[1] = ss;
    }
    __syncthreads();
    float inv = 1.0f / s_stat[1];

    float bestv = -1.0f;
    int besti = 0x7fffffff;
    for (int j = tid; j < VOCAB; j += 256) {
        float p = expf(row[j] - m) * inv;
        orow[j] = p;
        if (p > bestv) { bestv = p; besti = j; }
    }
    __shared__ float sv[256];
    __shared__ int si[256];
    sv[tid] = bestv;
    si[tid] = besti;
    __syncthreads();
    for (int st = 128; st > 0; st >>= 1) {
        if (tid < st) {
            float v2 = sv[tid + st];
            int i2 = si[tid + st];
            if (v2 > sv[tid] || (v2 == sv[tid] && i2 < si[tid])) {
                sv[tid] = v2;
                si[tid] = i2;
            }
        }
        __syncthreads();
    }
    if (tid == 0) g_tok[b] = si[0];
}

// ---------------------------------------------------------------------------
// Launch sequence (fully unrolled 32 steps; graph-capturable, alloc-free)
// ---------------------------------------------------------------------------
extern "C" void kernel_launch(void* const* d_in, const int* in_sizes, int n_in,
                              void* d_out, int out_size) {
    const float* enc     = (const float*)d_in[0];   // (128,64,2048)
    const float* ison    = (const float*)d_in[1];   // (128,64)
    const float* emb     = (const float*)d_in[2];   // (32000,512)
    const float* A1      = (const float*)d_in[3];   // (3072,512)
    const float* b1      = (const float*)d_in[4];   // (512)
    const float* A2v     = (const float*)d_in[5];   // (512,1)
    const float* b2      = (const float*)d_in[6];   // (1)
    const float* Wih0    = (const float*)d_in[7];   // (2560,4096)
    const float* WihR    = (const float*)d_in[8];   // (3,1024,4096)
    const float* Whh     = (const float*)d_in[9];   // (4,1024,4096)
    const float* bih     = (const float*)d_in[10];  // (4,4096)
    const float* bhh     = (const float*)d_in[11];  // (4,4096)
    const float* Wl      = (const float*)d_in[12];  // (3072,32000)
    const float* bl      = (const float*)d_in[13];  // (32000)
    const float* h0      = (const float*)d_in[14];  // (4,64,1024)
    const float* c0      = (const float*)d_in[15];  // (4,64,1024)
    const float* outr0   = (const float*)d_in[16];  // (64,1024)
    const int*   eos     = (const int*)d_in[17];    // scalar
    float* out = (float*)d_out;

    float* eproj;  cudaGetSymbolAddress((void**)&eproj,  g_enc_proj);
    float* xbuf;   cudaGetSymbolAddress((void**)&xbuf,   g_x);
    float* xlbuf;  cudaGetSymbolAddress((void**)&xlbuf,  g_xl);
    float* hbuf;   cudaGetSymbolAddress((void**)&hbuf,   g_h);
    float* cbuf;   cudaGetSymbolAddress((void**)&cbuf,   g_c);
    float* logits; cudaGetSymbolAddress((void**)&logits, g_logits);

    init_kernel<<<256, 256>>>(h0, c0, eos);

    // enc_proj = encoder(8192x2048) @ A1[H:](2048x512) + b1   [wide tiles]
    sgemm_t<128, 4, 8, 256><<<dim3(ADIM / 128, (T_IN * BATCH) / 64), 256>>>(
        enc, A1 + (size_t)HDIM * ADIM, 2 * HDIM, 2 * HDIM,
        b1, eproj, ADIM, 0);

    for (int step = 0; step < T_OUT; step++) {
        const float* outprev = (step == 0) ? outr0 : (hbuf + 3 * BATCH * HDIM);

        att_kernel<<<BATCH, 256>>>(enc, ison, emb, A1, A2v, b2, outprev);

        for (int l = 0; l < NLAYERS; l++) {
            const float* Ain = (l == 0) ? xbuf : (hbuf + (size_t)(l - 1) * BATCH * HDIM);
            int K1 = (l == 0) ? XDIM : HDIM;
            const float* Bih = (l == 0) ? Wih0 : (WihR + (size_t)(l - 1) * HDIM * GDIM);
            gates_splitk_kernel<<<dim3(GDIM / 64, KSPLIT), 256>>>(
                Ain, Bih, K1,
                hbuf + (size_t)l * BATCH * HDIM, Whh + (size_t)l * HDIM * GDIM);
            reduce_lstm_kernel<<<(BATCH * HDIM / 4) / 256, 256>>>(
                bih + (size_t)l * GDIM, bhh + (size_t)l * GDIM,
                hbuf + (size_t)l * BATCH * HDIM, cbuf + (size_t)l * BATCH * HDIM,
                (l == NLAYERS - 1) ? 1 : 0);
        }

        // logits = relu(xl(64x3072) @ Wl(3072x32000) + bl)   [wide tiles, 250 blocks]
        sgemm_t<128, 4, 8, 256><<<dim3(VOCAB / 128, 1), 256>>>(
            xlbuf, Wl, XLDIM, XLDIM,
            bl, logits, VOCAB, FLAG_RELU);

        softmax_argmax_kernel<<<BATCH, 256>>>(out, step);
    }
    (void)in_sizes; (void)n_in; (void)out_size;
}